// round 12
// baseline (speedup 1.0000x reference)
#include <cuda_runtime.h>
#include <cstdint>

#define IMG_H 512
#define IMG_W 512
#define N_IMG 16
#define WORDS_PER_ROW 16
#define WORDS_PER_IMG (IMG_H * WORDS_PER_ROW)   // 8192
#define PLANE (IMG_H * IMG_W)

__device__ unsigned g_strong[N_IMG * WORDS_PER_IMG];
__device__ unsigned g_weak  [N_IMG * WORDS_PER_IMG];
__device__ unsigned g_edge  [N_IMG * WORDS_PER_IMG];

__device__ __forceinline__ float gray_of(float r, float g, float b) {
    float v = __fadd_rn(__fadd_rn(__fmul_rn(0.2989f, r),
                                  __fmul_rn(0.587f, g)),
                        __fmul_rn(0.114f, b));
    return floorf(fminf(fmaxf(v, 0.0f), 255.0f));
}

// ---------------------------------------------------------------------------
// K1: gray -> sobel -> NMS -> strong/weak bitmasks. Batched over all images.
// Tile 32x64, blockDim (32,16). Interior blocks: float4 gray loads.
// ---------------------------------------------------------------------------
__global__ __launch_bounds__(512, 3) void canny_nms_kernel(const float* __restrict__ x) {
    const int img = blockIdx.z;
    const int tx0 = blockIdx.x * 32;
    const int ty0 = blockIdx.y * 64;

    __shared__ float gs[68][37];

    const int tx = threadIdx.x, ty = threadIdx.y;
    const int tid = ty * 32 + tx;
    const float* xb = x + (size_t)img * 3 * PLANE;

    // Phase 1: gray 68x36 (cols tx0-2..tx0+33).
    if (blockIdx.x > 0 && blockIdx.x < gridDim.x - 1) {
        // Interior: vectorized. Aligned float4 span cols tx0-4..tx0+35 (10 per row).
        for (int t = tid; t < 680; t += 512) {
            int r = t / 10;
            int k = t - r * 10;
            int gr = min(max(ty0 + r - 2, 0), IMG_H - 1);
            const float* rb = xb + gr * IMG_W + (tx0 - 4 + 4 * k);
            float4 v0 = __ldg((const float4*)rb);
            float4 v1 = __ldg((const float4*)(rb + PLANE));
            float4 v2 = __ldg((const float4*)(rb + 2 * PLANE));
            float g0 = gray_of(v0.x, v1.x, v2.x);
            float g1 = gray_of(v0.y, v1.y, v2.y);
            float g2 = gray_of(v0.z, v1.z, v2.z);
            float g3 = gray_of(v0.w, v1.w, v2.w);
            int cb = 4 * k - 2;   // gs column of element 0
            if ((unsigned)(cb    ) < 36u) gs[r][cb    ] = g0;
            if ((unsigned)(cb + 1) < 36u) gs[r][cb + 1] = g1;
            if ((unsigned)(cb + 2) < 36u) gs[r][cb + 2] = g2;
            if ((unsigned)(cb + 3) < 36u) gs[r][cb + 3] = g3;
        }
    } else {
        // Boundary blocks: scalar clamped path.
        for (int r = ty; r < 68; r += 16) {
            int gr = min(max(ty0 + r - 2, 0), IMG_H - 1);
            const float* rb = xb + gr * IMG_W;
            {
                int gc = min(max(tx0 + tx - 2, 0), IMG_W - 1);
                gs[r][tx] = gray_of(__ldg(rb + gc), __ldg(rb + PLANE + gc),
                                    __ldg(rb + 2 * PLANE + gc));
            }
            if (tx < 4) {
                int c = 32 + tx;
                int gc = min(max(tx0 + c - 2, 0), IMG_W - 1);
                gs[r][c] = gray_of(__ldg(rb + gc), __ldg(rb + PLANE + gc),
                                   __ldg(rb + 2 * PLANE + gc));
            }
        }
    }
    __syncthreads();

    const int y0 = ty * 4;

    // Phase 2: own-column mag rows j=0..5 (global row ty0+y0-1+j)
    float mag[6];
    unsigned cls = 0;
    {
        float c00 = gs[y0][tx + 1],     c01 = gs[y0][tx + 2],     c02 = gs[y0][tx + 3];
        float c10 = gs[y0 + 1][tx + 1], c11 = gs[y0 + 1][tx + 2], c12 = gs[y0 + 1][tx + 3];
#pragma unroll
        for (int j = 0; j < 6; j++) {
            float c20 = gs[y0 + j + 2][tx + 1];
            float c21 = gs[y0 + j + 2][tx + 2];
            float c22 = gs[y0 + j + 2][tx + 3];
            float gx = (c02 + 2.0f * c12 + c22) - (c00 + 2.0f * c10 + c20);
            float gy = (c20 + 2.0f * c21 + c22) - (c00 + 2.0f * c01 + c02);
            float ax = fabsf(gx), ay = fabsf(gy);
            int gm = ty0 + y0 - 1 + j;
            mag[j] = ((unsigned)gm < (unsigned)IMG_H) ? (ax + ay) : 0.0f;
            if (ay <= 0.4142135623730951f * ax) cls |= 1u << j;
            if (ay >  2.414213562373095f  * ax) cls |= 1u << (8 + j);
            if (gx * gy >= 0.0f)                cls |= 1u << (16 + j);
            c00 = c10; c01 = c11; c02 = c12;
            c10 = c20; c11 = c21; c12 = c22;
        }
    }

    // Distributed halo columns (lanes 0-11 compute one mag each; shuffle-route)
    float hv = 0.0f;
    if (tx < 12) {
        bool isL = tx < 6;
        int j  = isL ? tx : tx - 6;
        int cb = isL ? 0 : 33;
        bool valid = isL ? (blockIdx.x > 0) : (blockIdx.x < gridDim.x - 1);
        int gm = ty0 + y0 - 1 + j;
        if (valid && (unsigned)gm < (unsigned)IMG_H) {
            float a00 = gs[y0 + j][cb],     a01 = gs[y0 + j][cb + 1],     a02 = gs[y0 + j][cb + 2];
            float a10 = gs[y0 + j + 1][cb],                               a12 = gs[y0 + j + 1][cb + 2];
            float a20 = gs[y0 + j + 2][cb], a21 = gs[y0 + j + 2][cb + 1], a22 = gs[y0 + j + 2][cb + 2];
            float gx = (a02 + 2.0f * a12 + a22) - (a00 + 2.0f * a10 + a20);
            float gy = (a20 + 2.0f * a21 + a22) - (a00 + 2.0f * a01 + a02);
            hv = fabsf(gx) + fabsf(gy);
        }
    }
    float magH[6];
#pragma unroll
    for (int j = 0; j < 6; j++) {
        int src = (tx == 0) ? j : 6 + j;
        magH[j] = __shfl_sync(0xffffffffu, hv, src);
    }

    float magL[6], magR[6];
#pragma unroll
    for (int j = 0; j < 6; j++) {
        float l = __shfl_up_sync(0xffffffffu, mag[j], 1);
        float r = __shfl_down_sync(0xffffffffu, mag[j], 1);
        magL[j] = (tx == 0)  ? magH[j] : l;
        magR[j] = (tx == 31) ? magH[j] : r;
    }

#pragma unroll
    for (int k = 0; k < 4; k++) {
        int j = k + 1;
        float m = mag[j];
        bool horiz = (cls >> j) & 1u;
        bool vert  = (cls >> (8 + j)) & 1u;
        bool ssg   = (cls >> (16 + j)) & 1u;
        float n1 = horiz ? magR[j] : (vert ? mag[k]     : (ssg ? magL[k]     : magR[k]));
        float n2 = horiz ? magL[j] : (vert ? mag[k + 2] : (ssg ? magR[k + 2] : magL[k + 2]));
        bool keep = (m > n1) && (m >= n2);
        float nms = keep ? m : 0.0f;

        unsigned sb = __ballot_sync(0xffffffffu, nms > 150.0f);
        unsigned wb = __ballot_sync(0xffffffffu, nms > 50.0f);
        if (tx == 0) {
            int row = ty0 + y0 + k;
            int idx = (img * IMG_H + row) * WORDS_PER_ROW + blockIdx.x;
            g_strong[idx] = sb;
            g_weak[idx]   = wb;
        }
    }
}

// ---------------------------------------------------------------------------
// K2: hysteresis. 8-row x 32-col strip/thread, frontier gating, ALTERNATING
// single-direction Gauss-Seidel sweeps (half body vs down+up).
// Triggers dependent launch (K3) at entry so K3's loads overlap.
// ---------------------------------------------------------------------------
__device__ __forceinline__ unsigned Hd(unsigned m, unsigned l, unsigned r) {
    return m | (m << 1) | (m >> 1) | (l >> 31) | (r << 31);
}
__device__ __forceinline__ unsigned close_runs(unsigned g, unsigned w) {
    unsigned up = ((w + g) ^ w) & w;
    unsigned rg = __brev(g), rw = __brev(w);
    unsigned dn = __brev(((rw + rg) ^ rw) & rw);
    return g | up | dn;
}

__global__ __launch_bounds__(1024) void hysteresis_kernel() {
    asm volatile("griddepcontrol.launch_dependents;" ::: "memory");

    const int img = blockIdx.x;
    __shared__ unsigned cur[WORDS_PER_IMG];   // 32 KB
    __shared__ int chg[1024];                 // 4 KB
    const unsigned* wp = g_weak   + img * WORDS_PER_IMG;
    const unsigned* sp = g_strong + img * WORDS_PER_IMG;
    const int tid = threadIdx.x;
    const int w  = tid & 15;
    const int rg = tid >> 4;
    const int r0 = rg << 3;

    unsigned reg[8], wk[8];
#pragma unroll
    for (int i = 0; i < 8; i++) {
        int idx = (r0 + i) * 16 + w;
        reg[i] = sp[idx];
        wk[i]  = wp[idx];
        cur[idx] = reg[i];
    }
    chg[tid] = 1;
    __syncthreads();

    for (int sweep = 0; ; sweep++) {
        int need = chg[tid];
        {
            bool wl = (w > 0), wr = (w < 15);
            if (wl) need |= chg[tid - 1];
            if (wr) need |= chg[tid + 1];
            if (rg > 0) {
                need |= chg[tid - 16];
                if (wl) need |= chg[tid - 17];
                if (wr) need |= chg[tid - 15];
            }
            if (rg < 63) {
                need |= chg[tid + 16];
                if (wl) need |= chg[tid + 15];
                if (wr) need |= chg[tid + 17];
            }
        }

        unsigned changed = 0;
        if (need) {
            unsigned lw[10], rw[10];
#pragma unroll
            for (int j = 0; j < 10; j++) {
                int r = r0 - 1 + j;
                bool ok = (r >= 0 && r < IMG_H);
                lw[j] = (ok && w > 0)  ? cur[r * 16 + w - 1] : 0u;
                rw[j] = (ok && w < 15) ? cur[r * 16 + w + 1] : 0u;
            }
            unsigned ab = (r0 > 0)         ? cur[(r0 - 1) * 16 + w] : 0u;
            unsigned bl = (r0 + 8 < IMG_H) ? cur[(r0 + 8) * 16 + w] : 0u;

            if ((sweep & 1) == 0) {
#pragma unroll
                for (int i = 0; i < 8; i++) {     // down
                    unsigned up_row = (i == 0) ? ab : reg[i - 1];
                    unsigned dn_row = (i == 7) ? bl : reg[i + 1];
                    unsigned dil = Hd(up_row, lw[i], rw[i])
                                 | Hd(reg[i], lw[i + 1], rw[i + 1])
                                 | Hd(dn_row, lw[i + 2], rw[i + 2]);
                    unsigned g = reg[i] | (wk[i] & dil);
                    unsigned nv = g ? close_runs(g, wk[i]) : 0u;
                    changed |= nv ^ reg[i];
                    reg[i] = nv;
                }
            } else {
#pragma unroll
                for (int i = 7; i >= 0; i--) {    // up
                    unsigned up_row = (i == 0) ? ab : reg[i - 1];
                    unsigned dn_row = (i == 7) ? bl : reg[i + 1];
                    unsigned dil = Hd(up_row, lw[i], rw[i])
                                 | Hd(reg[i], lw[i + 1], rw[i + 1])
                                 | Hd(dn_row, lw[i + 2], rw[i + 2]);
                    unsigned g = reg[i] | (wk[i] & dil);
                    unsigned nv = g ? close_runs(g, wk[i]) : 0u;
                    changed |= nv ^ reg[i];
                    reg[i] = nv;
                }
            }
        }

        __syncthreads();
        if (changed) {
#pragma unroll
            for (int i = 0; i < 8; i++) cur[(r0 + i) * 16 + w] = reg[i];
        }
        chg[tid] = (changed != 0);
        if (!__syncthreads_or(changed != 0)) break;
    }

    unsigned* ep = g_edge + img * WORDS_PER_IMG;
#pragma unroll
    for (int i = 0; i < 8; i++) ep[(r0 + i) * 16 + w] = reg[i];
}

// ---------------------------------------------------------------------------
// K3: epilogue, 8 px/thread. PDL: all x loads issue BEFORE griddepcontrol.wait
// (overlap with K2, which triggers at entry). Streaming stores.
// ---------------------------------------------------------------------------
__global__ __launch_bounds__(256) void output_kernel(const float* __restrict__ x,
                                                     const float* __restrict__ Wm,
                                                     const float* __restrict__ bias,
                                                     float* __restrict__ out) {
    __shared__ float Ws[128];
    __shared__ float bs[32];
    const int tid = threadIdx.x;
    if (tid < 128) Ws[tid] = Wm[tid];
    if (tid < 32)  bs[tid] = bias[tid];

    const int gt  = blockIdx.x * 256 + tid;      // 524288 threads total
    const int img = gt >> 15;                    // 32768 threads per image
    const int pix = (gt & 32767) << 3;           // 8 px per thread

    // Pre-dependency phase: pull x while K2 is still running.
    const float* xb = x + (size_t)img * 3 * PLANE;
    float4 x0a = __ldg((const float4*)(xb + pix));
    float4 x0b = __ldg((const float4*)(xb + pix + 4));
    float4 x1a = __ldg((const float4*)(xb + PLANE + pix));
    float4 x1b = __ldg((const float4*)(xb + PLANE + pix + 4));
    float4 x2a = __ldg((const float4*)(xb + 2 * PLANE + pix));
    float4 x2b = __ldg((const float4*)(xb + 2 * PLANE + pix + 4));
    __syncthreads();   // Ws/bs ready

    asm volatile("griddepcontrol.wait;" ::: "memory");

    unsigned ew = g_edge[img * WORDS_PER_IMG + (pix >> 5)];
    int sh = pix & 31;
    float e[8];
#pragma unroll
    for (int i = 0; i < 8; i++)
        e[i] = ((ew >> (sh + i)) & 1u) ? 255.0f : 0.0f;

    float* ob = out + (size_t)img * 32 * PLANE + pix;
#pragma unroll 4
    for (int o = 0; o < 32; o++) {
        float w0 = Ws[4 * o], w1 = Ws[4 * o + 1], w2 = Ws[4 * o + 2], w3 = Ws[4 * o + 3];
        float bb = bs[o];
        float4 va, vb;
        va.x = fmaxf(fmaf(w0, x0a.x, fmaf(w1, x1a.x, fmaf(w2, x2a.x, fmaf(w3, e[0], bb)))), 0.0f);
        va.y = fmaxf(fmaf(w0, x0a.y, fmaf(w1, x1a.y, fmaf(w2, x2a.y, fmaf(w3, e[1], bb)))), 0.0f);
        va.z = fmaxf(fmaf(w0, x0a.z, fmaf(w1, x1a.z, fmaf(w2, x2a.z, fmaf(w3, e[2], bb)))), 0.0f);
        va.w = fmaxf(fmaf(w0, x0a.w, fmaf(w1, x1a.w, fmaf(w2, x2a.w, fmaf(w3, e[3], bb)))), 0.0f);
        vb.x = fmaxf(fmaf(w0, x0b.x, fmaf(w1, x1b.x, fmaf(w2, x2b.x, fmaf(w3, e[4], bb)))), 0.0f);
        vb.y = fmaxf(fmaf(w0, x0b.y, fmaf(w1, x1b.y, fmaf(w2, x2b.y, fmaf(w3, e[5], bb)))), 0.0f);
        vb.z = fmaxf(fmaf(w0, x0b.z, fmaf(w1, x1b.z, fmaf(w2, x2b.z, fmaf(w3, e[6], bb)))), 0.0f);
        vb.w = fmaxf(fmaf(w0, x0b.w, fmaf(w1, x1b.w, fmaf(w2, x2b.w, fmaf(w3, e[7], bb)))), 0.0f);
        float* op = ob + (size_t)o * PLANE;
        __stcs((float4*)op, va);
        __stcs((float4*)(op + 4), vb);
    }
}

// ---------------------------------------------------------------------------
extern "C" void kernel_launch(void* const* d_in, const int* in_sizes, int n_in,
                              void* d_out, int out_size) {
    (void)in_sizes; (void)n_in; (void)out_size;
    const float* x  = (const float*)d_in[0];
    const float* Wm = (const float*)d_in[1];
    const float* b  = (const float*)d_in[2];
    float* out = (float*)d_out;

    dim3 b1(32, 16), g1(IMG_W / 32, IMG_H / 64, N_IMG);
    canny_nms_kernel<<<g1, b1>>>(x);

    hysteresis_kernel<<<N_IMG, 1024>>>();

    cudaLaunchConfig_t cfg = {};
    cfg.gridDim  = dim3(N_IMG * PLANE / 8 / 256, 1, 1);   // 2048 blocks
    cfg.blockDim = dim3(256, 1, 1);
    cfg.dynamicSmemBytes = 0;
    cfg.stream = 0;
    cudaLaunchAttribute attrs[1];
    attrs[0].id = cudaLaunchAttributeProgrammaticStreamSerialization;
    attrs[0].val.programmaticStreamSerializationAllowed = 1;
    cfg.attrs = attrs;
    cfg.numAttrs = 1;
    cudaLaunchKernelEx(&cfg, output_kernel, x, Wm, b, out);
}

// round 13
// speedup vs baseline: 1.3900x; 1.3900x over previous
#include <cuda_runtime.h>
#include <cstdint>

#define IMG_H 512
#define IMG_W 512
#define N_IMG 16
#define WORDS_PER_ROW 16
#define WORDS_PER_IMG (IMG_H * WORDS_PER_ROW)   // 8192
#define PLANE (IMG_H * IMG_W)

__device__ unsigned g_strong[N_IMG * WORDS_PER_IMG];
__device__ unsigned g_weak  [N_IMG * WORDS_PER_IMG];
__device__ unsigned g_edge  [N_IMG * WORDS_PER_IMG];

__device__ __forceinline__ float gray_of(float r, float g, float b) {
    float v = __fadd_rn(__fadd_rn(__fmul_rn(0.2989f, r),
                                  __fmul_rn(0.587f, g)),
                        __fmul_rn(0.114f, b));
    return floorf(fminf(fmaxf(v, 0.0f), 255.0f));
}

// ---------------------------------------------------------------------------
// K1: gray -> sobel -> NMS -> strong/weak bitmasks. (R12 version, 26.3us)
// Tile 32x64, blockDim (32,16). Interior blocks: float4 gray loads.
// ---------------------------------------------------------------------------
__global__ __launch_bounds__(512, 3) void canny_nms_kernel(const float* __restrict__ x) {
    const int img = blockIdx.z;
    const int tx0 = blockIdx.x * 32;
    const int ty0 = blockIdx.y * 64;

    __shared__ float gs[68][37];

    const int tx = threadIdx.x, ty = threadIdx.y;
    const int tid = ty * 32 + tx;
    const float* xb = x + (size_t)img * 3 * PLANE;

    // Phase 1: gray 68x36 (cols tx0-2..tx0+33).
    if (blockIdx.x > 0 && blockIdx.x < gridDim.x - 1) {
        for (int t = tid; t < 680; t += 512) {
            int r = t / 10;
            int k = t - r * 10;
            int gr = min(max(ty0 + r - 2, 0), IMG_H - 1);
            const float* rb = xb + gr * IMG_W + (tx0 - 4 + 4 * k);
            float4 v0 = __ldg((const float4*)rb);
            float4 v1 = __ldg((const float4*)(rb + PLANE));
            float4 v2 = __ldg((const float4*)(rb + 2 * PLANE));
            float g0 = gray_of(v0.x, v1.x, v2.x);
            float g1 = gray_of(v0.y, v1.y, v2.y);
            float g2 = gray_of(v0.z, v1.z, v2.z);
            float g3 = gray_of(v0.w, v1.w, v2.w);
            int cb = 4 * k - 2;
            if ((unsigned)(cb    ) < 36u) gs[r][cb    ] = g0;
            if ((unsigned)(cb + 1) < 36u) gs[r][cb + 1] = g1;
            if ((unsigned)(cb + 2) < 36u) gs[r][cb + 2] = g2;
            if ((unsigned)(cb + 3) < 36u) gs[r][cb + 3] = g3;
        }
    } else {
        for (int r = ty; r < 68; r += 16) {
            int gr = min(max(ty0 + r - 2, 0), IMG_H - 1);
            const float* rb = xb + gr * IMG_W;
            {
                int gc = min(max(tx0 + tx - 2, 0), IMG_W - 1);
                gs[r][tx] = gray_of(__ldg(rb + gc), __ldg(rb + PLANE + gc),
                                    __ldg(rb + 2 * PLANE + gc));
            }
            if (tx < 4) {
                int c = 32 + tx;
                int gc = min(max(tx0 + c - 2, 0), IMG_W - 1);
                gs[r][c] = gray_of(__ldg(rb + gc), __ldg(rb + PLANE + gc),
                                   __ldg(rb + 2 * PLANE + gc));
            }
        }
    }
    __syncthreads();

    const int y0 = ty * 4;

    float mag[6];
    unsigned cls = 0;
    {
        float c00 = gs[y0][tx + 1],     c01 = gs[y0][tx + 2],     c02 = gs[y0][tx + 3];
        float c10 = gs[y0 + 1][tx + 1], c11 = gs[y0 + 1][tx + 2], c12 = gs[y0 + 1][tx + 3];
#pragma unroll
        for (int j = 0; j < 6; j++) {
            float c20 = gs[y0 + j + 2][tx + 1];
            float c21 = gs[y0 + j + 2][tx + 2];
            float c22 = gs[y0 + j + 2][tx + 3];
            float gx = (c02 + 2.0f * c12 + c22) - (c00 + 2.0f * c10 + c20);
            float gy = (c20 + 2.0f * c21 + c22) - (c00 + 2.0f * c01 + c02);
            float ax = fabsf(gx), ay = fabsf(gy);
            int gm = ty0 + y0 - 1 + j;
            mag[j] = ((unsigned)gm < (unsigned)IMG_H) ? (ax + ay) : 0.0f;
            if (ay <= 0.4142135623730951f * ax) cls |= 1u << j;
            if (ay >  2.414213562373095f  * ax) cls |= 1u << (8 + j);
            if (gx * gy >= 0.0f)                cls |= 1u << (16 + j);
            c00 = c10; c01 = c11; c02 = c12;
            c10 = c20; c11 = c21; c12 = c22;
        }
    }

    float hv = 0.0f;
    if (tx < 12) {
        bool isL = tx < 6;
        int j  = isL ? tx : tx - 6;
        int cb = isL ? 0 : 33;
        bool valid = isL ? (blockIdx.x > 0) : (blockIdx.x < gridDim.x - 1);
        int gm = ty0 + y0 - 1 + j;
        if (valid && (unsigned)gm < (unsigned)IMG_H) {
            float a00 = gs[y0 + j][cb],     a01 = gs[y0 + j][cb + 1],     a02 = gs[y0 + j][cb + 2];
            float a10 = gs[y0 + j + 1][cb],                               a12 = gs[y0 + j + 1][cb + 2];
            float a20 = gs[y0 + j + 2][cb], a21 = gs[y0 + j + 2][cb + 1], a22 = gs[y0 + j + 2][cb + 2];
            float gx = (a02 + 2.0f * a12 + a22) - (a00 + 2.0f * a10 + a20);
            float gy = (a20 + 2.0f * a21 + a22) - (a00 + 2.0f * a01 + a02);
            hv = fabsf(gx) + fabsf(gy);
        }
    }
    float magH[6];
#pragma unroll
    for (int j = 0; j < 6; j++) {
        int src = (tx == 0) ? j : 6 + j;
        magH[j] = __shfl_sync(0xffffffffu, hv, src);
    }

    float magL[6], magR[6];
#pragma unroll
    for (int j = 0; j < 6; j++) {
        float l = __shfl_up_sync(0xffffffffu, mag[j], 1);
        float r = __shfl_down_sync(0xffffffffu, mag[j], 1);
        magL[j] = (tx == 0)  ? magH[j] : l;
        magR[j] = (tx == 31) ? magH[j] : r;
    }

#pragma unroll
    for (int k = 0; k < 4; k++) {
        int j = k + 1;
        float m = mag[j];
        bool horiz = (cls >> j) & 1u;
        bool vert  = (cls >> (8 + j)) & 1u;
        bool ssg   = (cls >> (16 + j)) & 1u;
        float n1 = horiz ? magR[j] : (vert ? mag[k]     : (ssg ? magL[k]     : magR[k]));
        float n2 = horiz ? magL[j] : (vert ? mag[k + 2] : (ssg ? magR[k + 2] : magL[k + 2]));
        bool keep = (m > n1) && (m >= n2);
        float nms = keep ? m : 0.0f;

        unsigned sb = __ballot_sync(0xffffffffu, nms > 150.0f);
        unsigned wb = __ballot_sync(0xffffffffu, nms > 50.0f);
        if (tx == 0) {
            int row = ty0 + y0 + k;
            int idx = (img * IMG_H + row) * WORDS_PER_ROW + blockIdx.x;
            g_strong[idx] = sb;
            g_weak[idx]   = wb;
        }
    }
}

// ---------------------------------------------------------------------------
// K2: hysteresis (exact R10 version, 13.5us): down+up Gauss-Seidel per sweep,
// frontier gating, in-word run closure. No PDL, no boost.
// ---------------------------------------------------------------------------
__device__ __forceinline__ unsigned Hd(unsigned m, unsigned l, unsigned r) {
    return m | (m << 1) | (m >> 1) | (l >> 31) | (r << 31);
}
__device__ __forceinline__ unsigned close_runs(unsigned g, unsigned w) {
    unsigned up = ((w + g) ^ w) & w;
    unsigned rg = __brev(g), rw = __brev(w);
    unsigned dn = __brev(((rw + rg) ^ rw) & rw);
    return g | up | dn;
}

__global__ __launch_bounds__(1024) void hysteresis_kernel() {
    const int img = blockIdx.x;
    __shared__ unsigned cur[WORDS_PER_IMG];   // 32 KB
    __shared__ int chg[1024];                 // 4 KB
    const unsigned* wp = g_weak   + img * WORDS_PER_IMG;
    const unsigned* sp = g_strong + img * WORDS_PER_IMG;
    const int tid = threadIdx.x;
    const int w  = tid & 15;
    const int rg = tid >> 4;
    const int r0 = rg << 3;

    unsigned reg[8], wk[8];
#pragma unroll
    for (int i = 0; i < 8; i++) {
        int idx = (r0 + i) * 16 + w;
        reg[i] = sp[idx];
        wk[i]  = wp[idx];
        cur[idx] = reg[i];
    }
    chg[tid] = 1;
    __syncthreads();

    for (;;) {
        int need = chg[tid];
        {
            bool wl = (w > 0), wr = (w < 15);
            if (wl) need |= chg[tid - 1];
            if (wr) need |= chg[tid + 1];
            if (rg > 0) {
                need |= chg[tid - 16];
                if (wl) need |= chg[tid - 17];
                if (wr) need |= chg[tid - 15];
            }
            if (rg < 63) {
                need |= chg[tid + 16];
                if (wl) need |= chg[tid + 15];
                if (wr) need |= chg[tid + 17];
            }
        }

        unsigned changed = 0;
        if (need) {
            unsigned lw[10], rw[10];
#pragma unroll
            for (int j = 0; j < 10; j++) {
                int r = r0 - 1 + j;
                bool ok = (r >= 0 && r < IMG_H);
                lw[j] = (ok && w > 0)  ? cur[r * 16 + w - 1] : 0u;
                rw[j] = (ok && w < 15) ? cur[r * 16 + w + 1] : 0u;
            }
            unsigned ab = (r0 > 0)         ? cur[(r0 - 1) * 16 + w] : 0u;
            unsigned bl = (r0 + 8 < IMG_H) ? cur[(r0 + 8) * 16 + w] : 0u;

#pragma unroll
            for (int i = 0; i < 8; i++) {
                unsigned up_row = (i == 0) ? ab : reg[i - 1];
                unsigned dn_row = (i == 7) ? bl : reg[i + 1];
                unsigned dil = Hd(up_row, lw[i], rw[i])
                             | Hd(reg[i], lw[i + 1], rw[i + 1])
                             | Hd(dn_row, lw[i + 2], rw[i + 2]);
                unsigned g = reg[i] | (wk[i] & dil);
                unsigned nv = g ? close_runs(g, wk[i]) : 0u;
                changed |= nv ^ reg[i];
                reg[i] = nv;
            }
#pragma unroll
            for (int i = 7; i >= 0; i--) {
                unsigned up_row = (i == 0) ? ab : reg[i - 1];
                unsigned dn_row = (i == 7) ? bl : reg[i + 1];
                unsigned dil = Hd(up_row, lw[i], rw[i])
                             | Hd(reg[i], lw[i + 1], rw[i + 1])
                             | Hd(dn_row, lw[i + 2], rw[i + 2]);
                unsigned g = reg[i] | (wk[i] & dil);
                unsigned nv = g ? close_runs(g, wk[i]) : 0u;
                changed |= nv ^ reg[i];
                reg[i] = nv;
            }
        }

        __syncthreads();
        if (changed) {
#pragma unroll
            for (int i = 0; i < 8; i++) cur[(r0 + i) * 16 + w] = reg[i];
        }
        chg[tid] = (changed != 0);
        if (!__syncthreads_or(changed != 0)) break;
    }

    unsigned* ep = g_edge + img * WORDS_PER_IMG;
#pragma unroll
    for (int i = 0; i < 8; i++) ep[(r0 + i) * 16 + w] = reg[i];
}

// ---------------------------------------------------------------------------
// K3: epilogue (exact R11 4px/thread version). Plain launch, streaming stores.
// ---------------------------------------------------------------------------
__global__ __launch_bounds__(256) void output_kernel(const float* __restrict__ x,
                                                     const float* __restrict__ Wm,
                                                     const float* __restrict__ bias,
                                                     float* __restrict__ out) {
    __shared__ float Ws[128];
    __shared__ float bs[32];
    const int tid = threadIdx.x;
    if (tid < 128) Ws[tid] = Wm[tid];
    if (tid < 32)  bs[tid] = bias[tid];
    __syncthreads();

    const long gt  = (long)blockIdx.x * blockDim.x + tid;
    const int img  = (int)(gt >> 16);
    const int pix  = ((int)gt & 65535) << 2;

    const float* xb = x + (size_t)img * 3 * PLANE;
    float4 x0 = __ldg((const float4*)(xb + pix));
    float4 x1 = __ldg((const float4*)(xb + PLANE + pix));
    float4 x2 = __ldg((const float4*)(xb + 2 * PLANE + pix));

    unsigned ew = g_edge[img * WORDS_PER_IMG + (pix >> 5)];
    int sh = pix & 31;
    float e0 = ((ew >> (sh    )) & 1u) ? 255.0f : 0.0f;
    float e1 = ((ew >> (sh + 1)) & 1u) ? 255.0f : 0.0f;
    float e2 = ((ew >> (sh + 2)) & 1u) ? 255.0f : 0.0f;
    float e3 = ((ew >> (sh + 3)) & 1u) ? 255.0f : 0.0f;

    float* ob = out + (size_t)img * 32 * PLANE + pix;
#pragma unroll 8
    for (int o = 0; o < 32; o++) {
        float w0 = Ws[4 * o], w1 = Ws[4 * o + 1], w2 = Ws[4 * o + 2], w3 = Ws[4 * o + 3];
        float bb = bs[o];
        float4 v;
        v.x = fmaxf(fmaf(w0, x0.x, fmaf(w1, x1.x, fmaf(w2, x2.x, fmaf(w3, e0, bb)))), 0.0f);
        v.y = fmaxf(fmaf(w0, x0.y, fmaf(w1, x1.y, fmaf(w2, x2.y, fmaf(w3, e1, bb)))), 0.0f);
        v.z = fmaxf(fmaf(w0, x0.z, fmaf(w1, x1.z, fmaf(w2, x2.z, fmaf(w3, e2, bb)))), 0.0f);
        v.w = fmaxf(fmaf(w0, x0.w, fmaf(w1, x1.w, fmaf(w2, x2.w, fmaf(w3, e3, bb)))), 0.0f);
        __stcs((float4*)(ob + (size_t)o * PLANE), v);
    }
}

// ---------------------------------------------------------------------------
// Plain serial launch. No streams, no events, no PDL.
// ---------------------------------------------------------------------------
extern "C" void kernel_launch(void* const* d_in, const int* in_sizes, int n_in,
                              void* d_out, int out_size) {
    (void)in_sizes; (void)n_in; (void)out_size;
    const float* x  = (const float*)d_in[0];
    const float* Wm = (const float*)d_in[1];
    const float* b  = (const float*)d_in[2];
    float* out = (float*)d_out;

    dim3 b1(32, 16), g1(IMG_W / 32, IMG_H / 64, N_IMG);
    canny_nms_kernel<<<g1, b1>>>(x);

    hysteresis_kernel<<<N_IMG, 1024>>>();

    output_kernel<<<N_IMG * PLANE / 4 / 256, 256>>>(x, Wm, b, out);
}

// round 14
// speedup vs baseline: 1.4003x; 1.0074x over previous
#include <cuda_runtime.h>
#include <cstdint>

#define IMG_H 512
#define IMG_W 512
#define N_IMG 16
#define WORDS_PER_ROW 16                         // u32 words per row
#define WORDS_PER_IMG (IMG_H * WORDS_PER_ROW)    // 8192 u32
#define W64_PER_ROW 8                            // u64 words per row
#define W64_PER_IMG (IMG_H * W64_PER_ROW)        // 4096 u64
#define PLANE (IMG_H * IMG_W)

typedef unsigned long long u64;

__device__ __align__(16) unsigned g_strong[N_IMG * WORDS_PER_IMG];
__device__ __align__(16) unsigned g_weak  [N_IMG * WORDS_PER_IMG];
__device__ __align__(16) unsigned g_edge  [N_IMG * WORDS_PER_IMG];

__device__ __forceinline__ float gray_of(float r, float g, float b) {
    float v = __fadd_rn(__fadd_rn(__fmul_rn(0.2989f, r),
                                  __fmul_rn(0.587f, g)),
                        __fmul_rn(0.114f, b));
    return floorf(fminf(fmaxf(v, 0.0f), 255.0f));
}

// ---------------------------------------------------------------------------
// K1: gray -> sobel -> NMS -> strong/weak bitmasks. (R12/R13 version, 26.3us)
// ---------------------------------------------------------------------------
__global__ __launch_bounds__(512, 3) void canny_nms_kernel(const float* __restrict__ x) {
    const int img = blockIdx.z;
    const int tx0 = blockIdx.x * 32;
    const int ty0 = blockIdx.y * 64;

    __shared__ float gs[68][37];

    const int tx = threadIdx.x, ty = threadIdx.y;
    const int tid = ty * 32 + tx;
    const float* xb = x + (size_t)img * 3 * PLANE;

    if (blockIdx.x > 0 && blockIdx.x < gridDim.x - 1) {
        for (int t = tid; t < 680; t += 512) {
            int r = t / 10;
            int k = t - r * 10;
            int gr = min(max(ty0 + r - 2, 0), IMG_H - 1);
            const float* rb = xb + gr * IMG_W + (tx0 - 4 + 4 * k);
            float4 v0 = __ldg((const float4*)rb);
            float4 v1 = __ldg((const float4*)(rb + PLANE));
            float4 v2 = __ldg((const float4*)(rb + 2 * PLANE));
            float g0 = gray_of(v0.x, v1.x, v2.x);
            float g1 = gray_of(v0.y, v1.y, v2.y);
            float g2 = gray_of(v0.z, v1.z, v2.z);
            float g3 = gray_of(v0.w, v1.w, v2.w);
            int cb = 4 * k - 2;
            if ((unsigned)(cb    ) < 36u) gs[r][cb    ] = g0;
            if ((unsigned)(cb + 1) < 36u) gs[r][cb + 1] = g1;
            if ((unsigned)(cb + 2) < 36u) gs[r][cb + 2] = g2;
            if ((unsigned)(cb + 3) < 36u) gs[r][cb + 3] = g3;
        }
    } else {
        for (int r = ty; r < 68; r += 16) {
            int gr = min(max(ty0 + r - 2, 0), IMG_H - 1);
            const float* rb = xb + gr * IMG_W;
            {
                int gc = min(max(tx0 + tx - 2, 0), IMG_W - 1);
                gs[r][tx] = gray_of(__ldg(rb + gc), __ldg(rb + PLANE + gc),
                                    __ldg(rb + 2 * PLANE + gc));
            }
            if (tx < 4) {
                int c = 32 + tx;
                int gc = min(max(tx0 + c - 2, 0), IMG_W - 1);
                gs[r][c] = gray_of(__ldg(rb + gc), __ldg(rb + PLANE + gc),
                                   __ldg(rb + 2 * PLANE + gc));
            }
        }
    }
    __syncthreads();

    const int y0 = ty * 4;

    float mag[6];
    unsigned cls = 0;
    {
        float c00 = gs[y0][tx + 1],     c01 = gs[y0][tx + 2],     c02 = gs[y0][tx + 3];
        float c10 = gs[y0 + 1][tx + 1], c11 = gs[y0 + 1][tx + 2], c12 = gs[y0 + 1][tx + 3];
#pragma unroll
        for (int j = 0; j < 6; j++) {
            float c20 = gs[y0 + j + 2][tx + 1];
            float c21 = gs[y0 + j + 2][tx + 2];
            float c22 = gs[y0 + j + 2][tx + 3];
            float gx = (c02 + 2.0f * c12 + c22) - (c00 + 2.0f * c10 + c20);
            float gy = (c20 + 2.0f * c21 + c22) - (c00 + 2.0f * c01 + c02);
            float ax = fabsf(gx), ay = fabsf(gy);
            int gm = ty0 + y0 - 1 + j;
            mag[j] = ((unsigned)gm < (unsigned)IMG_H) ? (ax + ay) : 0.0f;
            if (ay <= 0.4142135623730951f * ax) cls |= 1u << j;
            if (ay >  2.414213562373095f  * ax) cls |= 1u << (8 + j);
            if (gx * gy >= 0.0f)                cls |= 1u << (16 + j);
            c00 = c10; c01 = c11; c02 = c12;
            c10 = c20; c11 = c21; c12 = c22;
        }
    }

    float hv = 0.0f;
    if (tx < 12) {
        bool isL = tx < 6;
        int j  = isL ? tx : tx - 6;
        int cb = isL ? 0 : 33;
        bool valid = isL ? (blockIdx.x > 0) : (blockIdx.x < gridDim.x - 1);
        int gm = ty0 + y0 - 1 + j;
        if (valid && (unsigned)gm < (unsigned)IMG_H) {
            float a00 = gs[y0 + j][cb],     a01 = gs[y0 + j][cb + 1],     a02 = gs[y0 + j][cb + 2];
            float a10 = gs[y0 + j + 1][cb],                               a12 = gs[y0 + j + 1][cb + 2];
            float a20 = gs[y0 + j + 2][cb], a21 = gs[y0 + j + 2][cb + 1], a22 = gs[y0 + j + 2][cb + 2];
            float gx = (a02 + 2.0f * a12 + a22) - (a00 + 2.0f * a10 + a20);
            float gy = (a20 + 2.0f * a21 + a22) - (a00 + 2.0f * a01 + a02);
            hv = fabsf(gx) + fabsf(gy);
        }
    }
    float magH[6];
#pragma unroll
    for (int j = 0; j < 6; j++) {
        int src = (tx == 0) ? j : 6 + j;
        magH[j] = __shfl_sync(0xffffffffu, hv, src);
    }

    float magL[6], magR[6];
#pragma unroll
    for (int j = 0; j < 6; j++) {
        float l = __shfl_up_sync(0xffffffffu, mag[j], 1);
        float r = __shfl_down_sync(0xffffffffu, mag[j], 1);
        magL[j] = (tx == 0)  ? magH[j] : l;
        magR[j] = (tx == 31) ? magH[j] : r;
    }

#pragma unroll
    for (int k = 0; k < 4; k++) {
        int j = k + 1;
        float m = mag[j];
        bool horiz = (cls >> j) & 1u;
        bool vert  = (cls >> (8 + j)) & 1u;
        bool ssg   = (cls >> (16 + j)) & 1u;
        float n1 = horiz ? magR[j] : (vert ? mag[k]     : (ssg ? magL[k]     : magR[k]));
        float n2 = horiz ? magL[j] : (vert ? mag[k + 2] : (ssg ? magR[k + 2] : magL[k + 2]));
        bool keep = (m > n1) && (m >= n2);
        float nms = keep ? m : 0.0f;

        unsigned sb = __ballot_sync(0xffffffffu, nms > 150.0f);
        unsigned wb = __ballot_sync(0xffffffffu, nms > 50.0f);
        if (tx == 0) {
            int row = ty0 + y0 + k;
            int idx = (img * IMG_H + row) * WORDS_PER_ROW + blockIdx.x;
            g_strong[idx] = sb;
            g_weak[idx]   = wb;
        }
    }
}

// ---------------------------------------------------------------------------
// K2: hysteresis in 64-bit words. Thread owns 8 rows x 64 cols (8 u64);
// 512 threads/block, one block per image. Down+up Gauss-Seidel + 64-bit
// in-word run closure + frontier gating. launch_dependents at entry (PDL).
// ---------------------------------------------------------------------------
__device__ __forceinline__ u64 Hd64(u64 m, u64 l, u64 r) {
    return m | (m << 1) | (m >> 1) | (l >> 63) | (r << 63);
}
__device__ __forceinline__ u64 close_runs64(u64 g, u64 w) {
    u64 up = ((w + g) ^ w) & w;
    u64 rg = __brevll(g), rw = __brevll(w);
    u64 dn = __brevll(((rw + rg) ^ rw) & rw);
    return g | up | dn;
}

__global__ __launch_bounds__(512) void hysteresis_kernel() {
    asm volatile("griddepcontrol.launch_dependents;" ::: "memory");

    const int img = blockIdx.x;
    __shared__ u64 cur[W64_PER_IMG];   // 32 KB
    __shared__ int chg[512];           // 2 KB
    const u64* wp = (const u64*)g_weak   + img * W64_PER_IMG;
    const u64* sp = (const u64*)g_strong + img * W64_PER_IMG;
    const int tid = threadIdx.x;
    const int w  = tid & 7;            // u64 word in row: 0..7
    const int rg = tid >> 3;           // rowgroup: 0..63
    const int r0 = rg << 3;

    u64 reg[8], wk[8];
#pragma unroll
    for (int i = 0; i < 8; i++) {
        int idx = (r0 + i) * W64_PER_ROW + w;
        reg[i] = sp[idx];
        wk[i]  = wp[idx];
        cur[idx] = reg[i];
    }
    chg[tid] = 1;
    __syncthreads();

    for (;;) {
        int need = chg[tid];
        {
            bool wl = (w > 0), wr = (w < 7);
            if (wl) need |= chg[tid - 1];
            if (wr) need |= chg[tid + 1];
            if (rg > 0) {
                need |= chg[tid - 8];
                if (wl) need |= chg[tid - 9];
                if (wr) need |= chg[tid - 7];
            }
            if (rg < 63) {
                need |= chg[tid + 8];
                if (wl) need |= chg[tid + 7];
                if (wr) need |= chg[tid + 9];
            }
        }

        u64 changed = 0;
        if (need) {
            u64 lw[10], rw[10];
#pragma unroll
            for (int j = 0; j < 10; j++) {
                int r = r0 - 1 + j;
                bool ok = (r >= 0 && r < IMG_H);
                lw[j] = (ok && w > 0) ? cur[r * W64_PER_ROW + w - 1] : 0ull;
                rw[j] = (ok && w < 7) ? cur[r * W64_PER_ROW + w + 1] : 0ull;
            }
            u64 ab = (r0 > 0)         ? cur[(r0 - 1) * W64_PER_ROW + w] : 0ull;
            u64 bl = (r0 + 8 < IMG_H) ? cur[(r0 + 8) * W64_PER_ROW + w] : 0ull;

#pragma unroll
            for (int i = 0; i < 8; i++) {     // down
                u64 up_row = (i == 0) ? ab : reg[i - 1];
                u64 dn_row = (i == 7) ? bl : reg[i + 1];
                u64 dil = Hd64(up_row, lw[i], rw[i])
                        | Hd64(reg[i], lw[i + 1], rw[i + 1])
                        | Hd64(dn_row, lw[i + 2], rw[i + 2]);
                u64 g = reg[i] | (wk[i] & dil);
                u64 nv = g ? close_runs64(g, wk[i]) : 0ull;
                changed |= nv ^ reg[i];
                reg[i] = nv;
            }
#pragma unroll
            for (int i = 7; i >= 0; i--) {    // up
                u64 up_row = (i == 0) ? ab : reg[i - 1];
                u64 dn_row = (i == 7) ? bl : reg[i + 1];
                u64 dil = Hd64(up_row, lw[i], rw[i])
                        | Hd64(reg[i], lw[i + 1], rw[i + 1])
                        | Hd64(dn_row, lw[i + 2], rw[i + 2]);
                u64 g = reg[i] | (wk[i] & dil);
                u64 nv = g ? close_runs64(g, wk[i]) : 0ull;
                changed |= nv ^ reg[i];
                reg[i] = nv;
            }
        }

        __syncthreads();
        if (changed) {
#pragma unroll
            for (int i = 0; i < 8; i++) cur[(r0 + i) * W64_PER_ROW + w] = reg[i];
        }
        chg[tid] = (changed != 0ull);
        if (!__syncthreads_or(changed != 0ull)) break;
    }

    u64* ep = (u64*)g_edge + img * W64_PER_IMG;
#pragma unroll
    for (int i = 0; i < 8; i++) ep[(r0 + i) * W64_PER_ROW + w] = reg[i];
}

// ---------------------------------------------------------------------------
// K3: epilogue, 4 px/thread (R13-measured store pattern). PDL: x loads issue
// before griddepcontrol.wait; g_edge read after. Streaming stores.
// ---------------------------------------------------------------------------
__global__ __launch_bounds__(256) void output_kernel(const float* __restrict__ x,
                                                     const float* __restrict__ Wm,
                                                     const float* __restrict__ bias,
                                                     float* __restrict__ out) {
    __shared__ float Ws[128];
    __shared__ float bs[32];
    const int tid = threadIdx.x;
    if (tid < 128) Ws[tid] = Wm[tid];
    if (tid < 32)  bs[tid] = bias[tid];

    const long gt  = (long)blockIdx.x * blockDim.x + tid;
    const int img  = (int)(gt >> 16);
    const int pix  = ((int)gt & 65535) << 2;

    const float* xb = x + (size_t)img * 3 * PLANE;
    float4 x0 = __ldg((const float4*)(xb + pix));
    float4 x1 = __ldg((const float4*)(xb + PLANE + pix));
    float4 x2 = __ldg((const float4*)(xb + 2 * PLANE + pix));
    __syncthreads();   // Ws/bs ready

    asm volatile("griddepcontrol.wait;" ::: "memory");

    unsigned ew = g_edge[img * WORDS_PER_IMG + (pix >> 5)];
    int sh = pix & 31;
    float e0 = ((ew >> (sh    )) & 1u) ? 255.0f : 0.0f;
    float e1 = ((ew >> (sh + 1)) & 1u) ? 255.0f : 0.0f;
    float e2 = ((ew >> (sh + 2)) & 1u) ? 255.0f : 0.0f;
    float e3 = ((ew >> (sh + 3)) & 1u) ? 255.0f : 0.0f;

    float* ob = out + (size_t)img * 32 * PLANE + pix;
#pragma unroll 8
    for (int o = 0; o < 32; o++) {
        float w0 = Ws[4 * o], w1 = Ws[4 * o + 1], w2 = Ws[4 * o + 2], w3 = Ws[4 * o + 3];
        float bb = bs[o];
        float4 v;
        v.x = fmaxf(fmaf(w0, x0.x, fmaf(w1, x1.x, fmaf(w2, x2.x, fmaf(w3, e0, bb)))), 0.0f);
        v.y = fmaxf(fmaf(w0, x0.y, fmaf(w1, x1.y, fmaf(w2, x2.y, fmaf(w3, e1, bb)))), 0.0f);
        v.z = fmaxf(fmaf(w0, x0.z, fmaf(w1, x1.z, fmaf(w2, x2.z, fmaf(w3, e2, bb)))), 0.0f);
        v.w = fmaxf(fmaf(w0, x0.w, fmaf(w1, x1.w, fmaf(w2, x2.w, fmaf(w3, e3, bb)))), 0.0f);
        __stcs((float4*)(ob + (size_t)o * PLANE), v);
    }
}

// ---------------------------------------------------------------------------
extern "C" void kernel_launch(void* const* d_in, const int* in_sizes, int n_in,
                              void* d_out, int out_size) {
    (void)in_sizes; (void)n_in; (void)out_size;
    const float* x  = (const float*)d_in[0];
    const float* Wm = (const float*)d_in[1];
    const float* b  = (const float*)d_in[2];
    float* out = (float*)d_out;

    dim3 b1(32, 16), g1(IMG_W / 32, IMG_H / 64, N_IMG);
    canny_nms_kernel<<<g1, b1>>>(x);

    hysteresis_kernel<<<N_IMG, 512>>>();

    cudaLaunchConfig_t cfg = {};
    cfg.gridDim  = dim3(N_IMG * PLANE / 4 / 256, 1, 1);
    cfg.blockDim = dim3(256, 1, 1);
    cfg.dynamicSmemBytes = 0;
    cfg.stream = 0;
    cudaLaunchAttribute attrs[1];
    attrs[0].id = cudaLaunchAttributeProgrammaticStreamSerialization;
    attrs[0].val.programmaticStreamSerializationAllowed = 1;
    cfg.attrs = attrs;
    cfg.numAttrs = 1;
    cudaLaunchKernelEx(&cfg, output_kernel, x, Wm, b, out);
}

// round 15
// speedup vs baseline: 1.4237x; 1.0168x over previous
#include <cuda_runtime.h>
#include <cstdint>

#define IMG_H 512
#define IMG_W 512
#define N_IMG 16
#define WORDS_PER_ROW 16                         // u32 words per row
#define WORDS_PER_IMG (IMG_H * WORDS_PER_ROW)    // 8192 u32
#define W64_PER_ROW 8                            // u64 words per row
#define W64_PER_IMG (IMG_H * W64_PER_ROW)        // 4096 u64
#define PLANE (IMG_H * IMG_W)

typedef unsigned long long u64;

__device__ __align__(16) unsigned g_strong[N_IMG * WORDS_PER_IMG];
__device__ __align__(16) unsigned g_weak  [N_IMG * WORDS_PER_IMG];
__device__ __align__(16) unsigned g_edge  [N_IMG * WORDS_PER_IMG];

__device__ __forceinline__ float gray_of(float r, float g, float b) {
    float v = __fadd_rn(__fadd_rn(__fmul_rn(0.2989f, r),
                                  __fmul_rn(0.587f, g)),
                        __fmul_rn(0.114f, b));
    return floorf(fminf(fmaxf(v, 0.0f), 255.0f));
}

// ---------------------------------------------------------------------------
// K1: gray -> sobel -> NMS -> strong/weak bitmasks.
// ONLY change vs R14: __launch_bounds__(512, 4) => 32 regs, 4 blocks/SM.
// ---------------------------------------------------------------------------
__global__ __launch_bounds__(512, 4) void canny_nms_kernel(const float* __restrict__ x) {
    const int img = blockIdx.z;
    const int tx0 = blockIdx.x * 32;
    const int ty0 = blockIdx.y * 64;

    __shared__ float gs[68][37];

    const int tx = threadIdx.x, ty = threadIdx.y;
    const int tid = ty * 32 + tx;
    const float* xb = x + (size_t)img * 3 * PLANE;

    if (blockIdx.x > 0 && blockIdx.x < gridDim.x - 1) {
        for (int t = tid; t < 680; t += 512) {
            int r = t / 10;
            int k = t - r * 10;
            int gr = min(max(ty0 + r - 2, 0), IMG_H - 1);
            const float* rb = xb + gr * IMG_W + (tx0 - 4 + 4 * k);
            float4 v0 = __ldg((const float4*)rb);
            float4 v1 = __ldg((const float4*)(rb + PLANE));
            float4 v2 = __ldg((const float4*)(rb + 2 * PLANE));
            float g0 = gray_of(v0.x, v1.x, v2.x);
            float g1 = gray_of(v0.y, v1.y, v2.y);
            float g2 = gray_of(v0.z, v1.z, v2.z);
            float g3 = gray_of(v0.w, v1.w, v2.w);
            int cb = 4 * k - 2;
            if ((unsigned)(cb    ) < 36u) gs[r][cb    ] = g0;
            if ((unsigned)(cb + 1) < 36u) gs[r][cb + 1] = g1;
            if ((unsigned)(cb + 2) < 36u) gs[r][cb + 2] = g2;
            if ((unsigned)(cb + 3) < 36u) gs[r][cb + 3] = g3;
        }
    } else {
        for (int r = ty; r < 68; r += 16) {
            int gr = min(max(ty0 + r - 2, 0), IMG_H - 1);
            const float* rb = xb + gr * IMG_W;
            {
                int gc = min(max(tx0 + tx - 2, 0), IMG_W - 1);
                gs[r][tx] = gray_of(__ldg(rb + gc), __ldg(rb + PLANE + gc),
                                    __ldg(rb + 2 * PLANE + gc));
            }
            if (tx < 4) {
                int c = 32 + tx;
                int gc = min(max(tx0 + c - 2, 0), IMG_W - 1);
                gs[r][c] = gray_of(__ldg(rb + gc), __ldg(rb + PLANE + gc),
                                   __ldg(rb + 2 * PLANE + gc));
            }
        }
    }
    __syncthreads();

    const int y0 = ty * 4;

    float mag[6];
    unsigned cls = 0;
    {
        float c00 = gs[y0][tx + 1],     c01 = gs[y0][tx + 2],     c02 = gs[y0][tx + 3];
        float c10 = gs[y0 + 1][tx + 1], c11 = gs[y0 + 1][tx + 2], c12 = gs[y0 + 1][tx + 3];
#pragma unroll
        for (int j = 0; j < 6; j++) {
            float c20 = gs[y0 + j + 2][tx + 1];
            float c21 = gs[y0 + j + 2][tx + 2];
            float c22 = gs[y0 + j + 2][tx + 3];
            float gx = (c02 + 2.0f * c12 + c22) - (c00 + 2.0f * c10 + c20);
            float gy = (c20 + 2.0f * c21 + c22) - (c00 + 2.0f * c01 + c02);
            float ax = fabsf(gx), ay = fabsf(gy);
            int gm = ty0 + y0 - 1 + j;
            mag[j] = ((unsigned)gm < (unsigned)IMG_H) ? (ax + ay) : 0.0f;
            if (ay <= 0.4142135623730951f * ax) cls |= 1u << j;
            if (ay >  2.414213562373095f  * ax) cls |= 1u << (8 + j);
            if (gx * gy >= 0.0f)                cls |= 1u << (16 + j);
            c00 = c10; c01 = c11; c02 = c12;
            c10 = c20; c11 = c21; c12 = c22;
        }
    }

    float hv = 0.0f;
    if (tx < 12) {
        bool isL = tx < 6;
        int j  = isL ? tx : tx - 6;
        int cb = isL ? 0 : 33;
        bool valid = isL ? (blockIdx.x > 0) : (blockIdx.x < gridDim.x - 1);
        int gm = ty0 + y0 - 1 + j;
        if (valid && (unsigned)gm < (unsigned)IMG_H) {
            float a00 = gs[y0 + j][cb],     a01 = gs[y0 + j][cb + 1],     a02 = gs[y0 + j][cb + 2];
            float a10 = gs[y0 + j + 1][cb],                               a12 = gs[y0 + j + 1][cb + 2];
            float a20 = gs[y0 + j + 2][cb], a21 = gs[y0 + j + 2][cb + 1], a22 = gs[y0 + j + 2][cb + 2];
            float gx = (a02 + 2.0f * a12 + a22) - (a00 + 2.0f * a10 + a20);
            float gy = (a20 + 2.0f * a21 + a22) - (a00 + 2.0f * a01 + a02);
            hv = fabsf(gx) + fabsf(gy);
        }
    }
    float magH[6];
#pragma unroll
    for (int j = 0; j < 6; j++) {
        int src = (tx == 0) ? j : 6 + j;
        magH[j] = __shfl_sync(0xffffffffu, hv, src);
    }

    float magL[6], magR[6];
#pragma unroll
    for (int j = 0; j < 6; j++) {
        float l = __shfl_up_sync(0xffffffffu, mag[j], 1);
        float r = __shfl_down_sync(0xffffffffu, mag[j], 1);
        magL[j] = (tx == 0)  ? magH[j] : l;
        magR[j] = (tx == 31) ? magH[j] : r;
    }

#pragma unroll
    for (int k = 0; k < 4; k++) {
        int j = k + 1;
        float m = mag[j];
        bool horiz = (cls >> j) & 1u;
        bool vert  = (cls >> (8 + j)) & 1u;
        bool ssg   = (cls >> (16 + j)) & 1u;
        float n1 = horiz ? magR[j] : (vert ? mag[k]     : (ssg ? magL[k]     : magR[k]));
        float n2 = horiz ? magL[j] : (vert ? mag[k + 2] : (ssg ? magR[k + 2] : magL[k + 2]));
        bool keep = (m > n1) && (m >= n2);
        float nms = keep ? m : 0.0f;

        unsigned sb = __ballot_sync(0xffffffffu, nms > 150.0f);
        unsigned wb = __ballot_sync(0xffffffffu, nms > 50.0f);
        if (tx == 0) {
            int row = ty0 + y0 + k;
            int idx = (img * IMG_H + row) * WORDS_PER_ROW + blockIdx.x;
            g_strong[idx] = sb;
            g_weak[idx]   = wb;
        }
    }
}

// ---------------------------------------------------------------------------
// K2: hysteresis in u64 (R14 version). launch_dependents at entry.
// ---------------------------------------------------------------------------
__device__ __forceinline__ u64 Hd64(u64 m, u64 l, u64 r) {
    return m | (m << 1) | (m >> 1) | (l >> 63) | (r << 63);
}
__device__ __forceinline__ u64 close_runs64(u64 g, u64 w) {
    u64 up = ((w + g) ^ w) & w;
    u64 rg = __brevll(g), rw = __brevll(w);
    u64 dn = __brevll(((rw + rg) ^ rw) & rw);
    return g | up | dn;
}

__global__ __launch_bounds__(512) void hysteresis_kernel() {
    asm volatile("griddepcontrol.launch_dependents;" ::: "memory");

    const int img = blockIdx.x;
    __shared__ u64 cur[W64_PER_IMG];   // 32 KB
    __shared__ int chg[512];           // 2 KB
    const u64* wp = (const u64*)g_weak   + img * W64_PER_IMG;
    const u64* sp = (const u64*)g_strong + img * W64_PER_IMG;
    const int tid = threadIdx.x;
    const int w  = tid & 7;
    const int rg = tid >> 3;
    const int r0 = rg << 3;

    u64 reg[8], wk[8];
#pragma unroll
    for (int i = 0; i < 8; i++) {
        int idx = (r0 + i) * W64_PER_ROW + w;
        reg[i] = sp[idx];
        wk[i]  = wp[idx];
        cur[idx] = reg[i];
    }
    chg[tid] = 1;
    __syncthreads();

    for (;;) {
        int need = chg[tid];
        {
            bool wl = (w > 0), wr = (w < 7);
            if (wl) need |= chg[tid - 1];
            if (wr) need |= chg[tid + 1];
            if (rg > 0) {
                need |= chg[tid - 8];
                if (wl) need |= chg[tid - 9];
                if (wr) need |= chg[tid - 7];
            }
            if (rg < 63) {
                need |= chg[tid + 8];
                if (wl) need |= chg[tid + 7];
                if (wr) need |= chg[tid + 9];
            }
        }

        u64 changed = 0;
        if (need) {
            u64 lw[10], rw[10];
#pragma unroll
            for (int j = 0; j < 10; j++) {
                int r = r0 - 1 + j;
                bool ok = (r >= 0 && r < IMG_H);
                lw[j] = (ok && w > 0) ? cur[r * W64_PER_ROW + w - 1] : 0ull;
                rw[j] = (ok && w < 7) ? cur[r * W64_PER_ROW + w + 1] : 0ull;
            }
            u64 ab = (r0 > 0)         ? cur[(r0 - 1) * W64_PER_ROW + w] : 0ull;
            u64 bl = (r0 + 8 < IMG_H) ? cur[(r0 + 8) * W64_PER_ROW + w] : 0ull;

#pragma unroll
            for (int i = 0; i < 8; i++) {
                u64 up_row = (i == 0) ? ab : reg[i - 1];
                u64 dn_row = (i == 7) ? bl : reg[i + 1];
                u64 dil = Hd64(up_row, lw[i], rw[i])
                        | Hd64(reg[i], lw[i + 1], rw[i + 1])
                        | Hd64(dn_row, lw[i + 2], rw[i + 2]);
                u64 g = reg[i] | (wk[i] & dil);
                u64 nv = g ? close_runs64(g, wk[i]) : 0ull;
                changed |= nv ^ reg[i];
                reg[i] = nv;
            }
#pragma unroll
            for (int i = 7; i >= 0; i--) {
                u64 up_row = (i == 0) ? ab : reg[i - 1];
                u64 dn_row = (i == 7) ? bl : reg[i + 1];
                u64 dil = Hd64(up_row, lw[i], rw[i])
                        | Hd64(reg[i], lw[i + 1], rw[i + 1])
                        | Hd64(dn_row, lw[i + 2], rw[i + 2]);
                u64 g = reg[i] | (wk[i] & dil);
                u64 nv = g ? close_runs64(g, wk[i]) : 0ull;
                changed |= nv ^ reg[i];
                reg[i] = nv;
            }
        }

        __syncthreads();
        if (changed) {
#pragma unroll
            for (int i = 0; i < 8; i++) cur[(r0 + i) * W64_PER_ROW + w] = reg[i];
        }
        chg[tid] = (changed != 0ull);
        if (!__syncthreads_or(changed != 0ull)) break;
    }

    u64* ep = (u64*)g_edge + img * W64_PER_IMG;
#pragma unroll
    for (int i = 0; i < 8; i++) ep[(r0 + i) * W64_PER_ROW + w] = reg[i];
}

// ---------------------------------------------------------------------------
// K3: epilogue, 4 px/thread, PDL pre-wait loads, streaming stores. (R14)
// ---------------------------------------------------------------------------
__global__ __launch_bounds__(256) void output_kernel(const float* __restrict__ x,
                                                     const float* __restrict__ Wm,
                                                     const float* __restrict__ bias,
                                                     float* __restrict__ out) {
    __shared__ float Ws[128];
    __shared__ float bs[32];
    const int tid = threadIdx.x;
    if (tid < 128) Ws[tid] = Wm[tid];
    if (tid < 32)  bs[tid] = bias[tid];

    const long gt  = (long)blockIdx.x * blockDim.x + tid;
    const int img  = (int)(gt >> 16);
    const int pix  = ((int)gt & 65535) << 2;

    const float* xb = x + (size_t)img * 3 * PLANE;
    float4 x0 = __ldg((const float4*)(xb + pix));
    float4 x1 = __ldg((const float4*)(xb + PLANE + pix));
    float4 x2 = __ldg((const float4*)(xb + 2 * PLANE + pix));
    __syncthreads();

    asm volatile("griddepcontrol.wait;" ::: "memory");

    unsigned ew = g_edge[img * WORDS_PER_IMG + (pix >> 5)];
    int sh = pix & 31;
    float e0 = ((ew >> (sh    )) & 1u) ? 255.0f : 0.0f;
    float e1 = ((ew >> (sh + 1)) & 1u) ? 255.0f : 0.0f;
    float e2 = ((ew >> (sh + 2)) & 1u) ? 255.0f : 0.0f;
    float e3 = ((ew >> (sh + 3)) & 1u) ? 255.0f : 0.0f;

    float* ob = out + (size_t)img * 32 * PLANE + pix;
#pragma unroll 8
    for (int o = 0; o < 32; o++) {
        float w0 = Ws[4 * o], w1 = Ws[4 * o + 1], w2 = Ws[4 * o + 2], w3 = Ws[4 * o + 3];
        float bb = bs[o];
        float4 v;
        v.x = fmaxf(fmaf(w0, x0.x, fmaf(w1, x1.x, fmaf(w2, x2.x, fmaf(w3, e0, bb)))), 0.0f);
        v.y = fmaxf(fmaf(w0, x0.y, fmaf(w1, x1.y, fmaf(w2, x2.y, fmaf(w3, e1, bb)))), 0.0f);
        v.z = fmaxf(fmaf(w0, x0.z, fmaf(w1, x1.z, fmaf(w2, x2.z, fmaf(w3, e2, bb)))), 0.0f);
        v.w = fmaxf(fmaf(w0, x0.w, fmaf(w1, x1.w, fmaf(w2, x2.w, fmaf(w3, e3, bb)))), 0.0f);
        __stcs((float4*)(ob + (size_t)o * PLANE), v);
    }
}

// ---------------------------------------------------------------------------
extern "C" void kernel_launch(void* const* d_in, const int* in_sizes, int n_in,
                              void* d_out, int out_size) {
    (void)in_sizes; (void)n_in; (void)out_size;
    const float* x  = (const float*)d_in[0];
    const float* Wm = (const float*)d_in[1];
    const float* b  = (const float*)d_in[2];
    float* out = (float*)d_out;

    dim3 b1(32, 16), g1(IMG_W / 32, IMG_H / 64, N_IMG);
    canny_nms_kernel<<<g1, b1>>>(x);

    hysteresis_kernel<<<N_IMG, 512>>>();

    cudaLaunchConfig_t cfg = {};
    cfg.gridDim  = dim3(N_IMG * PLANE / 4 / 256, 1, 1);
    cfg.blockDim = dim3(256, 1, 1);
    cfg.dynamicSmemBytes = 0;
    cfg.stream = 0;
    cudaLaunchAttribute attrs[1];
    attrs[0].id = cudaLaunchAttributeProgrammaticStreamSerialization;
    attrs[0].val.programmaticStreamSerializationAllowed = 1;
    cfg.attrs = attrs;
    cfg.numAttrs = 1;
    cudaLaunchKernelEx(&cfg, output_kernel, x, Wm, b, out);
}